// round 1
// baseline (speedup 1.0000x reference)
#include <cuda_runtime.h>

#define NUM_HEADS 4
#define WORD_DIM 100
#define NWORDS 39            // W-1
#define W_TOTAL 40
#define LEAKY_ALPHA 0.3f
#define PAD 101              // words row stride in smem (101 mod 32 = 5, coprime -> conflict-free)
#define NTHREADS 256
#define TILE_FLOATS (W_TOTAL * WORD_DIM)   // 4000 floats per (b,t,e) group
#define TILE_VEC4 (TILE_FLOATS / 4)        // 1000 float4

__global__ __launch_bounds__(NTHREADS)
void tse_kernel(const float* __restrict__ x,
                const float* __restrict__ w_att,
                const float* __restrict__ b_att,
                float* __restrict__ out,
                int n_groups)
{
    __shared__ float s_words[NWORDS * PAD];      // 39 x 100 padded to 101
    __shared__ float s_type[WORD_DIM];
    __shared__ float s_watt[NUM_HEADS * WORD_DIM];
    __shared__ float s_batt[NUM_HEADS * WORD_DIM];
    __shared__ float s_e[NUM_HEADS * NWORDS];    // exp(scores)
    __shared__ float s_inv[NUM_HEADS];
    __shared__ int   s_nz;

    const int tid = threadIdx.x;
    const int group = blockIdx.x;
    if (group >= n_groups) return;

    if (tid == 0) s_nz = 0;

    // load attention params (L2-resident across blocks)
    for (int i = tid; i < NUM_HEADS * WORD_DIM; i += NTHREADS) {
        s_watt[i] = w_att[i];
        s_batt[i] = b_att[i];
    }
    __syncthreads();   // also orders s_nz init before atomicOr below

    // ---- phase 1: stage the 40x100 tile (float4, coalesced), track nonzero ----
    const float4* __restrict__ gx4 =
        reinterpret_cast<const float4*>(x + (size_t)group * TILE_FLOATS);
    bool flag = false;
    #pragma unroll 2
    for (int i4 = tid; i4 < TILE_VEC4; i4 += NTHREADS) {
        float4 v = gx4[i4];
        flag |= (v.x != 0.f) | (v.y != 0.f) | (v.z != 0.f) | (v.w != 0.f);
        int e0 = i4 * 4;
        int w  = e0 / WORD_DIM;       // 100 % 4 == 0 -> vector stays in one row
        int d  = e0 - w * WORD_DIM;
        if (w == 0) {
            s_type[d + 0] = v.x; s_type[d + 1] = v.y;
            s_type[d + 2] = v.z; s_type[d + 3] = v.w;
        } else {
            float* r = &s_words[(w - 1) * PAD + d];
            r[0] = v.x; r[1] = v.y; r[2] = v.z; r[3] = v.w;
        }
    }
    unsigned any = __ballot_sync(0xffffffffu, flag);
    if ((tid & 31) == 0 && any) atomicOr(&s_nz, 1);
    __syncthreads();

    // ---- phase 2: scores -> exp, one (h,n) per thread (156 active) ----
    if (tid < NUM_HEADS * NWORDS) {
        const int h = tid / NWORDS;
        const int n = tid - h * NWORDS;
        const float* __restrict__ wr = &s_words[n * PAD];
        const float* __restrict__ wa = &s_watt[h * WORD_DIM];
        const float* __restrict__ ba = &s_batt[h * WORD_DIM];
        float acc = 0.f;
        #pragma unroll 4
        for (int d = 0; d < WORD_DIM; ++d) {
            float p = fmaf(wr[d], wa[d], ba[d]);
            float hd = p >= 0.f ? p : LEAKY_ALPHA * p;
            acc = fmaf(s_type[d], hd, acc);
        }
        s_e[tid] = expf(acc);
    }
    __syncthreads();

    // ---- phase 3: per-head softmax denominator (warp h reduces head h) ----
    const int warp = tid >> 5, lane = tid & 31;
    if (warp < NUM_HEADS) {
        float v = s_e[warp * NWORDS + lane % NWORDS];  // placeholder avoided: compute properly
        v = s_e[warp * NWORDS + (lane < NWORDS ? lane : 0)] * (lane < NWORDS ? 1.f : 0.f);
        if (lane < NWORDS - 32) v += s_e[warp * NWORDS + 32 + lane];
        #pragma unroll
        for (int off = 16; off > 0; off >>= 1)
            v += __shfl_down_sync(0xffffffffu, v, off);
        if (lane == 0) s_inv[warp] = 1.f / v;
    }
    __syncthreads();

    // ---- phase 4: out[h][d] = inv[h] * sum_n e[h][n] * words[n][d] ----
    const int nz = s_nz;
    float* __restrict__ go = out + (size_t)group * (NUM_HEADS * WORD_DIM);
    #pragma unroll
    for (int idx = tid; idx < NUM_HEADS * WORD_DIM; idx += NTHREADS) {
        const int h = idx / WORD_DIM;
        const int d = idx - h * WORD_DIM;
        const float* __restrict__ eh = &s_e[h * NWORDS];
        float acc = 0.f;
        #pragma unroll 13
        for (int n = 0; n < NWORDS; ++n)
            acc = fmaf(eh[n], s_words[n * PAD + d], acc);
        go[idx] = nz ? acc * s_inv[h] : 0.f;
    }
}

extern "C" void kernel_launch(void* const* d_in, const int* in_sizes, int n_in,
                              void* d_out, int out_size)
{
    const float* x     = (const float*)d_in[0];
    const float* w_att = (const float*)d_in[1];
    const float* b_att = (const float*)d_in[2];
    float* out = (float*)d_out;

    int n_groups = in_sizes[0] / TILE_FLOATS;   // B*T*E = 4800
    tse_kernel<<<n_groups, NTHREADS>>>(x, w_att, b_att, out, n_groups);
}

// round 2
// speedup vs baseline: 1.4439x; 1.4439x over previous
#include <cuda_runtime.h>

#define NUM_HEADS 4
#define D 100               // WORD_DIM
#define D4 25               // D/4
#define NW 39               // words per group (W-1)
#define ALPHA 0.3f
#define NT 160
#define TILE_FLOATS 4000    // 40*100 per (b,t,e) group
#define TILE_VEC4 1000

__global__ __launch_bounds__(NT)
void tse_kernel(const float* __restrict__ x,
                const float* __restrict__ w_att,
                const float* __restrict__ b_att,
                float* __restrict__ out,
                int n_groups)
{
    __shared__ float  s_words[NW * D];                 // 15.6 KB, row stride 100 (float4-aligned)
    __shared__ float  s_type[D];
    __shared__ float4 s_wab[NUM_HEADS * D4 * 2];       // (h,j) -> [wa4, ba4] interleaved
    __shared__ float4 s_e4[NW];                        // exp(scores) for 4 heads per word
    __shared__ float4 s_part[2];
    __shared__ float4 s_inv4;
    __shared__ int    s_nz;

    const int t = threadIdx.x;
    const int g = blockIdx.x;
    if (g >= n_groups) return;

    // ---- phase 0: init + params (interleaved float4 pack; L2-resident source) ----
    if (t == 0) s_nz = 0;
    {
        float* wab_f = (float*)s_wab;
        for (int i = t; i < NUM_HEADS * D; i += NT) {
            int h = i / D, d = i - h * D;
            int j = d >> 2, c = d & 3;
            wab_f[(((h * D4 + j) * 2) + 0) * 4 + c] = w_att[i];
            wab_f[(((h * D4 + j) * 2) + 1) * 4 + c] = b_att[i];
        }
    }
    __syncthreads();   // orders s_nz init before atomicOr below

    // ---- phase 1: stage 40x100 tile, float4 LDG + float4 STS (conflict-free) ----
    const float4* __restrict__ gx4 =
        reinterpret_cast<const float4*>(x + (size_t)g * TILE_FLOATS);
    bool flag = false;
    for (int i4 = t; i4 < TILE_VEC4; i4 += NT) {
        float4 v = gx4[i4];
        flag |= (v.x != 0.f) | (v.y != 0.f) | (v.z != 0.f) | (v.w != 0.f);
        int e0 = i4 << 2;
        int w  = e0 / D;                 // 100 % 4 == 0: vector stays in one row
        int d  = e0 - w * D;
        if (w == 0) *reinterpret_cast<float4*>(&s_type[d]) = v;
        else        *reinterpret_cast<float4*>(&s_words[(w - 1) * D + d]) = v;
    }
    unsigned any = __ballot_sync(0xffffffffu, flag);
    if ((t & 31) == 0 && any) atomicOr(&s_nz, 1);
    __syncthreads();

    // ---- phase 2: thread t < 39 owns word t, computes all 4 head scores ----
    // words read ONCE; params/type are 1-wavefront float4 broadcasts.
    float e0 = 0.f, e1 = 0.f, e2 = 0.f, e3 = 0.f;
    if (t < NW) {
        const float4* __restrict__ wr4 = reinterpret_cast<const float4*>(&s_words[t * D]);
        const float4* __restrict__ ty4 = reinterpret_cast<const float4*>(s_type);
        float a[NUM_HEADS] = {0.f, 0.f, 0.f, 0.f};
        #pragma unroll 5
        for (int j = 0; j < D4; ++j) {
            float4 w  = wr4[j];
            float4 ty = ty4[j];
            #pragma unroll
            for (int h = 0; h < NUM_HEADS; ++h) {
                float4 wa = s_wab[(h * D4 + j) * 2 + 0];
                float4 ba = s_wab[(h * D4 + j) * 2 + 1];
                float p, hd, acc = a[h];
                p = fmaf(w.x, wa.x, ba.x); hd = p >= 0.f ? p : ALPHA * p; acc = fmaf(ty.x, hd, acc);
                p = fmaf(w.y, wa.y, ba.y); hd = p >= 0.f ? p : ALPHA * p; acc = fmaf(ty.y, hd, acc);
                p = fmaf(w.z, wa.z, ba.z); hd = p >= 0.f ? p : ALPHA * p; acc = fmaf(ty.z, hd, acc);
                p = fmaf(w.w, wa.w, ba.w); hd = p >= 0.f ? p : ALPHA * p; acc = fmaf(ty.w, hd, acc);
                a[h] = acc;
            }
        }
        e0 = expf(a[0]); e1 = expf(a[1]); e2 = expf(a[2]); e3 = expf(a[3]);
        s_e4[t] = make_float4(e0, e1, e2, e3);
    }

    // ---- phase 3: softmax denominators via warp shuffle (warps 0,1 only) ----
    if (t < 64) {
        #pragma unroll
        for (int off = 16; off; off >>= 1) {
            e0 += __shfl_down_sync(0xffffffffu, e0, off);
            e1 += __shfl_down_sync(0xffffffffu, e1, off);
            e2 += __shfl_down_sync(0xffffffffu, e2, off);
            e3 += __shfl_down_sync(0xffffffffu, e3, off);
        }
        if ((t & 31) == 0) s_part[t >> 5] = make_float4(e0, e1, e2, e3);
    }
    __syncthreads();
    if (t == 0) {
        float4 p0 = s_part[0], p1 = s_part[1];
        s_inv4 = make_float4(1.f / (p0.x + p1.x), 1.f / (p0.y + p1.y),
                             1.f / (p0.z + p1.z), 1.f / (p0.w + p1.w));
    }
    __syncthreads();

    // ---- phase 4: thread t < 100 owns column d=t, accumulates all 4 heads ----
    // words read ONCE (1 spread wf/n), e4 is a single LDS.128 broadcast per n.
    if (t < D) {
        const int nz = s_nz;
        float a0 = 0.f, a1 = 0.f, a2 = 0.f, a3 = 0.f;
        #pragma unroll
        for (int n = 0; n < NW; ++n) {
            float  w = s_words[n * D + t];
            float4 e = s_e4[n];
            a0 = fmaf(e.x, w, a0);
            a1 = fmaf(e.y, w, a1);
            a2 = fmaf(e.z, w, a2);
            a3 = fmaf(e.w, w, a3);
        }
        float4 inv = s_inv4;
        float* __restrict__ go = out + (size_t)g * (NUM_HEADS * D);
        if (nz) {
            go[t]         = a0 * inv.x;
            go[D + t]     = a1 * inv.y;
            go[2 * D + t] = a2 * inv.z;
            go[3 * D + t] = a3 * inv.w;
        } else {
            go[t] = 0.f; go[D + t] = 0.f; go[2 * D + t] = 0.f; go[3 * D + t] = 0.f;
        }
    }
}

extern "C" void kernel_launch(void* const* d_in, const int* in_sizes, int n_in,
                              void* d_out, int out_size)
{
    const float* x     = (const float*)d_in[0];
    const float* w_att = (const float*)d_in[1];
    const float* b_att = (const float*)d_in[2];
    float* out = (float*)d_out;

    int n_groups = in_sizes[0] / TILE_FLOATS;   // B*T*E = 4800
    tse_kernel<<<n_groups, NT>>>(x, w_att, b_att, out, n_groups);
}